// round 10
// baseline (speedup 1.0000x reference)
#include <cuda_runtime.h>
#include <cstdint>

// Problem constants (fixed by the dataset)
#define BATCH   128
#define IN_DIM  2048
#define HID     2048
#define OUT_DIM 512
#define TSTEPS  32
#define VDECAY  0.5f
#define VTH     0.5f
#define KCHUNK  512   // reference split-K chunk (bit-exact contract from R2)

#define TB (TSTEPS * BATCH)   // 4096 batched rows

// ---------------- device scratch (no allocations allowed) ----------------
__device__ float g_xt[TB * IN_DIM];      // [T*B, K] transposed input
__device__ float g_g0[TB * HID];         // layer0 raw GEMM results
__device__ float g_s0all[TB * HID];      // layer0 spikes per t
__device__ float g_g1[TB * HID];         // layer1 raw GEMM results
__device__ float g_s1all[TB * HID];      // layer1 spikes per t
__device__ float g_go[TB * OUT_DIM];     // output-layer raw GEMM results

// packed f32x2 ops: two independent IEEE-RN operations per instruction ->
// per-element rounding identical to scalar chains (validated bit-exact in R8).
#define FMA2(accv, av, wv) \
    asm("fma.rn.f32x2 %0, %1, %2, %0;" : "+l"(accv) : "l"(av), "l"(wv))
#define ADD2(totv, accv) \
    asm("add.rn.f32x2 %0, %0, %1;" : "+l"(totv) : "l"(accv))

// ---------------- transpose spike_data [B, K, T] -> [T, B, K] ----------------
__global__ void transpose_kernel(const float* __restrict__ sd) {
    __shared__ float tile[32][33];
    int b  = blockIdx.y;
    int k0 = blockIdx.x * 32;
    int tx = threadIdx.x;
    int ty = threadIdx.y;
#pragma unroll
    for (int i = 0; i < 4; i++) {
        int kl = ty + i * 8;
        tile[kl][tx] = sd[(b * IN_DIM + k0 + kl) * TSTEPS + tx];
    }
    __syncthreads();
#pragma unroll
    for (int i = 0; i < 4; i++) {
        int t = ty + i * 8;
        g_xt[(t * BATCH + b) * IN_DIM + k0 + tx] = tile[tx][t];
    }
}

// ---------------- LIF scan over time (elementwise, hidden layers) ----------------
template <int N>
__global__ void lif_scan_kernel(const float* __restrict__ gin,   // [T, B*N]
                                float* __restrict__ sall,        // [T, B*N]
                                const float* __restrict__ v0in,
                                const float* __restrict__ s0in,
                                const float* __restrict__ bias) {
    int idx = blockIdx.x * blockDim.x + threadIdx.x;
    if (idx >= BATCH * N) return;
    float vv = v0in[idx];
    float ss = s0in[idx];
    float bb = bias[idx % N];
#pragma unroll
    for (int t = 0; t < TSTEPS; t++) {
        float g = gin[(size_t)t * BATCH * N + idx];
        float decay = __fmul_rn(__fmul_rn(VDECAY, vv), __fadd_rn(1.0f, -ss));
        vv = __fadd_rn(__fadd_rn(decay, g), bb);
        ss = (vv > VTH) ? 1.0f : 0.0f;
        sall[(size_t)t * BATCH * N + idx] = ss;
    }
}

// ---------------- output-layer LIF scan: accumulate spike counts ----------------
__global__ void lifo_scan_kernel(const float* __restrict__ gin,
                                 const float* __restrict__ v0in,
                                 const float* __restrict__ s0in,
                                 const float* __restrict__ bias,
                                 float* __restrict__ out) {
    int idx = blockIdx.x * blockDim.x + threadIdx.x;
    if (idx >= BATCH * OUT_DIM) return;
    float vv = v0in[idx];
    float ss = s0in[idx];
    float bb = bias[idx % OUT_DIM];
    float acc = 0.0f;
#pragma unroll
    for (int t = 0; t < TSTEPS; t++) {
        float g = gin[(size_t)t * BATCH * OUT_DIM + idx];
        float decay = __fmul_rn(__fmul_rn(VDECAY, vv), __fadd_rn(1.0f, -ss));
        vv = __fadd_rn(__fadd_rn(decay, g), bb);
        ss = (vv > VTH) ? 1.0f : 0.0f;
        acc += ss;
    }
    out[idx] = acc;
}

// ---------------- double-buffered GEMM, packed f32x2, high occupancy ----------------
// C[m][n] = sum_k X[m][k]*W[n][k]. Rounding contract (bit-exact since R2):
// serial in-order FMA per element within each 512-chunk, chunks folded
// left-associatively. X is stored DUPLICATED in smem ((x,x) adjacent pairs),
// so the packed a-operand needs no mov-packing in the inner loop.
// Tiles: BM=32, BN=64, 128 threads, thread tile 4x4; 6 CTAs/SM target.
template <int N, int KTOT>
__global__ __launch_bounds__(128, 6) void gemm_kernel(
    const float* __restrict__ X,
    const float* __restrict__ W,
    float* __restrict__ out)
{
    constexpr int BK  = 16;
    constexpr int BM  = 32;
    constexpr int BN  = 64;
    constexpr int NT  = KTOT / BK;
    constexpr int CH  = KCHUNK / BK;       // 32 tiles per rounding chunk
    constexpr int XLD = 4;                 // BM*BK/128
    constexpr int WLD = 8;                 // BN*BK/128
    constexpr int XROW = 2 * BM + 4;       // 68 floats, 16B-multiple
    constexpr int WROW = BN + 4;           // 68

    __shared__ __align__(16) float Xsd[2][BK][XROW];   // duplicated X pairs
    __shared__ __align__(16) float Ws[2][BK][WROW];

    const int tid = threadIdx.x;
    const int m0 = blockIdx.y * BM;
    const int n0 = blockIdx.x * BN;

    const int lk = tid % BK;
    const int lr = tid / BK;               // 0..7
    const float* Xp = X + (size_t)(m0 + lr) * KTOT + lk;
    const float* Wp = W + (size_t)(n0 + lr) * KTOT + lk;

    const int tx = tid % 16;               // cols tx*4..tx*4+3
    const int ty = tid / 16;               // 0..7 -> rows ty*4..ty*4+3

    float xr[XLD], wr[WLD];
    // acc[i][j]: row ty*4+i ; j -> cols tx*4+{2j, 2j+1}
    unsigned long long acc[4][2], tot[4][2];
#pragma unroll
    for (int i = 0; i < 4; i++)
#pragma unroll
        for (int j = 0; j < 2; j++) { acc[i][j] = 0ull; tot[i][j] = 0ull; }

    // prologue: tile0 -> regs -> buf0 ; tile1 -> regs (in flight)
#pragma unroll
    for (int i = 0; i < XLD; i++) xr[i] = Xp[(size_t)i * 8 * KTOT];
#pragma unroll
    for (int i = 0; i < WLD; i++) wr[i] = Wp[(size_t)i * 8 * KTOT];
#pragma unroll
    for (int i = 0; i < XLD; i++) {
        Xsd[0][lk][2 * (lr + i * 8)]     = xr[i];
        Xsd[0][lk][2 * (lr + i * 8) + 1] = xr[i];
    }
#pragma unroll
    for (int i = 0; i < WLD; i++) Ws[0][lk][lr + i * 8] = wr[i];
#pragma unroll
    for (int i = 0; i < XLD; i++) xr[i] = Xp[(size_t)i * 8 * KTOT + BK];
#pragma unroll
    for (int i = 0; i < WLD; i++) wr[i] = Wp[(size_t)i * 8 * KTOT + BK];
    __syncthreads();

    for (int t = 0; t < NT; t++) {
        const int cur = t & 1;
        if (t + 1 < NT) {
#pragma unroll
            for (int i = 0; i < XLD; i++) {
                Xsd[cur ^ 1][lk][2 * (lr + i * 8)]     = xr[i];
                Xsd[cur ^ 1][lk][2 * (lr + i * 8) + 1] = xr[i];
            }
#pragma unroll
            for (int i = 0; i < WLD; i++) Ws[cur ^ 1][lk][lr + i * 8] = wr[i];
        }
        if (t + 2 < NT) {
#pragma unroll
            for (int i = 0; i < XLD; i++) xr[i] = Xp[(size_t)i * 8 * KTOT + (t + 2) * BK];
#pragma unroll
            for (int i = 0; i < WLD; i++) wr[i] = Wp[(size_t)i * 8 * KTOT + (t + 2) * BK];
        }

#pragma unroll
        for (int kk = 0; kk < BK; kk++) {
            // duplicated pairs: (x0,x0),(x1,x1) and (x2,x2),(x3,x3) — broadcast LDS
            ulonglong2 xa = *reinterpret_cast<const ulonglong2*>(&Xsd[cur][kk][ty * 8]);
            ulonglong2 xb = *reinterpret_cast<const ulonglong2*>(&Xsd[cur][kk][ty * 8 + 4]);
            ulonglong2 wv = *reinterpret_cast<const ulonglong2*>(&Ws[cur][kk][tx * 4]);
            FMA2(acc[0][0], xa.x, wv.x);
            FMA2(acc[0][1], xa.x, wv.y);
            FMA2(acc[1][0], xa.y, wv.x);
            FMA2(acc[1][1], xa.y, wv.y);
            FMA2(acc[2][0], xb.x, wv.x);
            FMA2(acc[2][1], xb.x, wv.y);
            FMA2(acc[3][0], xb.y, wv.x);
            FMA2(acc[3][1], xb.y, wv.y);
        }

        if ((t & (CH - 1)) == (CH - 1)) {
            // fold chunk (left-associative per element), reset chunk accumulator
#pragma unroll
            for (int i = 0; i < 4; i++)
#pragma unroll
                for (int j = 0; j < 2; j++) {
                    ADD2(tot[i][j], acc[i][j]);
                    acc[i][j] = 0ull;
                }
        }
        __syncthreads();
    }

    // epilogue: raw store of folded sums (float4 per row)
#pragma unroll
    for (int i = 0; i < 4; i++) {
        float4 f4;
        f4.x = __uint_as_float((uint32_t)(tot[i][0] & 0xFFFFFFFFull));
        f4.y = __uint_as_float((uint32_t)(tot[i][0] >> 32));
        f4.z = __uint_as_float((uint32_t)(tot[i][1] & 0xFFFFFFFFull));
        f4.w = __uint_as_float((uint32_t)(tot[i][1] >> 32));
        *reinterpret_cast<float4*>(out + (size_t)(m0 + ty * 4 + i) * N + n0 + tx * 4) = f4;
    }
}

// ---------------- launcher ----------------
extern "C" void kernel_launch(void* const* d_in, const int* in_sizes, int n_in,
                              void* d_out, int out_size) {
    (void)in_sizes; (void)n_in; (void)out_size;
    const float* sd  = (const float*)d_in[0];
    const float* h0v = (const float*)d_in[1];
    const float* h0s = (const float*)d_in[2];
    const float* h1v = (const float*)d_in[3];
    const float* h1s = (const float*)d_in[4];
    const float* ov  = (const float*)d_in[5];
    const float* os  = (const float*)d_in[6];
    const float* W0  = (const float*)d_in[7];
    const float* b0  = (const float*)d_in[8];
    const float* W1  = (const float*)d_in[9];
    const float* b1  = (const float*)d_in[10];
    const float* Wo  = (const float*)d_in[11];
    const float* bo  = (const float*)d_in[12];
    float* out = (float*)d_out;

    float *xt, *gg0, *s0all, *gg1, *s1all, *ggo;
    cudaGetSymbolAddress((void**)&xt,    g_xt);
    cudaGetSymbolAddress((void**)&gg0,   g_g0);
    cudaGetSymbolAddress((void**)&s0all, g_s0all);
    cudaGetSymbolAddress((void**)&gg1,   g_g1);
    cudaGetSymbolAddress((void**)&s1all, g_s1all);
    cudaGetSymbolAddress((void**)&ggo,   g_go);

    // 1) transpose input [B,K,T] -> [T,B,K]
    {
        dim3 tb(32, 8);
        dim3 tg(IN_DIM / 32, BATCH);
        transpose_kernel<<<tg, tb>>>(sd);
    }

    // 2) layer0 GEMM batched over all timesteps (M = T*B = 4096)
    {
        dim3 grid(HID / 64, TB / 32);   // (32, 128) = 4096 CTAs
        gemm_kernel<HID, IN_DIM><<<grid, 128>>>(xt, W0, gg0);
    }

    // 3) layer0 LIF scan
    lif_scan_kernel<HID><<<(BATCH * HID + 255) / 256, 256>>>(gg0, s0all, h0v, h0s, b0);

    // 4) layer1 GEMM
    {
        dim3 grid(HID / 64, TB / 32);
        gemm_kernel<HID, HID><<<grid, 128>>>(s0all, W1, gg1);
    }

    // 5) layer1 LIF scan
    lif_scan_kernel<HID><<<(BATCH * HID + 255) / 256, 256>>>(gg1, s1all, h1v, h1s, b1);

    // 6) output-layer GEMM
    {
        dim3 grid(OUT_DIM / 64, TB / 32);   // (8, 128) = 1024 CTAs
        gemm_kernel<OUT_DIM, HID><<<grid, 128>>>(s1all, Wo, ggo);
    }

    // 7) output LIF scan + spike-count accumulation
    lifo_scan_kernel<<<(BATCH * OUT_DIM + 255) / 256, 256>>>(ggo, ov, os, bo, out);
}

// round 11
// speedup vs baseline: 1.9784x; 1.9784x over previous
#include <cuda_runtime.h>
#include <cstdint>

// Problem constants (fixed by the dataset)
#define BATCH   128
#define IN_DIM  2048
#define HID     2048
#define OUT_DIM 512
#define TSTEPS  32
#define VDECAY  0.5f
#define VTH     0.5f
#define KCHUNK  512   // reference split-K chunk (bit-exact contract from R2)

#define TB (TSTEPS * BATCH)   // 4096 batched rows

// ---------------- device scratch (no allocations allowed) ----------------
__device__ float g_xt[TB * IN_DIM];          // [T*B, K] transposed input
__device__ float g_p0[4 * TB * HID];         // layer0 chunk partials [z][T*B, H]
__device__ float g_s0all[TB * HID];          // layer0 spikes per t
__device__ float g_p1[4 * TB * HID];         // layer1 chunk partials
__device__ float g_s1all[TB * HID];          // layer1 spikes per t
__device__ float g_po[4 * TB * OUT_DIM];     // output-layer chunk partials

// packed f32x2 ops: two independent IEEE-RN operations per instruction ->
// per-element rounding identical to scalar chains (validated bit-exact in R8).
#define FMA2(accv, av, wv) \
    asm("fma.rn.f32x2 %0, %1, %2, %0;" : "+l"(accv) : "l"(av), "l"(wv))
#define DUP2(dst, fval) \
    asm("mov.b64 %0, {%1, %1};" : "=l"(dst) : "r"(__float_as_uint(fval)))

// ---------------- transpose spike_data [B, K, T] -> [T, B, K] ----------------
__global__ void transpose_kernel(const float* __restrict__ sd) {
    __shared__ float tile[32][33];
    int b  = blockIdx.y;
    int k0 = blockIdx.x * 32;
    int tx = threadIdx.x;
    int ty = threadIdx.y;
#pragma unroll
    for (int i = 0; i < 4; i++) {
        int kl = ty + i * 8;
        tile[kl][tx] = sd[(b * IN_DIM + k0 + kl) * TSTEPS + tx];
    }
    __syncthreads();
#pragma unroll
    for (int i = 0; i < 4; i++) {
        int t = ty + i * 8;
        g_xt[(t * BATCH + b) * IN_DIM + k0 + tx] = tile[tx][t];
    }
}

// ---------------- LIF scan over time (folds 4 chunk partials) ----------------
// g = ((p0+p1)+p2)+p3 left-assoc (== in-kernel fold since 0+c0 rounds to c0);
// then v = (0.5*v*(1-s) + g) + bias ; s = (v > VTH). Bit-exact contract.
template <int N>
__global__ void lif_scan_kernel(const float* __restrict__ pin,   // [4][T*B*N]
                                float* __restrict__ sall,        // [T, B*N]
                                const float* __restrict__ v0in,
                                const float* __restrict__ s0in,
                                const float* __restrict__ bias) {
    int idx = blockIdx.x * blockDim.x + threadIdx.x;
    if (idx >= BATCH * N) return;
    const size_t PL = (size_t)TB * N;    // plane stride
    float vv = v0in[idx];
    float ss = s0in[idx];
    float bb = bias[idx % N];
#pragma unroll
    for (int t = 0; t < TSTEPS; t++) {
        size_t o = (size_t)t * BATCH * N + idx;
        float g = __fadd_rn(__fadd_rn(__fadd_rn(pin[o], pin[PL + o]), pin[2 * PL + o]),
                            pin[3 * PL + o]);
        float decay = __fmul_rn(__fmul_rn(VDECAY, vv), __fadd_rn(1.0f, -ss));
        vv = __fadd_rn(__fadd_rn(decay, g), bb);
        ss = (vv > VTH) ? 1.0f : 0.0f;
        sall[o] = ss;
    }
}

// ---------------- output-layer LIF scan: fold partials + spike counts ----------------
__global__ void lifo_scan_kernel(const float* __restrict__ pin,  // [4][T*B*OUT]
                                 const float* __restrict__ v0in,
                                 const float* __restrict__ s0in,
                                 const float* __restrict__ bias,
                                 float* __restrict__ out) {
    int idx = blockIdx.x * blockDim.x + threadIdx.x;
    if (idx >= BATCH * OUT_DIM) return;
    const size_t PL = (size_t)TB * OUT_DIM;
    float vv = v0in[idx];
    float ss = s0in[idx];
    float bb = bias[idx % OUT_DIM];
    float acc = 0.0f;
#pragma unroll
    for (int t = 0; t < TSTEPS; t++) {
        size_t o = (size_t)t * BATCH * OUT_DIM + idx;
        float g = __fadd_rn(__fadd_rn(__fadd_rn(pin[o], pin[PL + o]), pin[2 * PL + o]),
                            pin[3 * PL + o]);
        float decay = __fmul_rn(__fmul_rn(VDECAY, vv), __fadd_rn(1.0f, -ss));
        vv = __fadd_rn(__fadd_rn(decay, g), bb);
        ss = (vv > VTH) ? 1.0f : 0.0f;
        acc += ss;
    }
    out[idx] = acc;
}

// ---------------- split-K chunk GEMM, packed f32x2, TM8xTN8 ----------------
// Partial[z][m][n] = sum over k in [z*512, z*512+512) of X[m][k]*W[n][k],
// serial in-order FMA per element (bit-exact chunk chain from R2 contract).
// BM=64, BN=128, 128 threads; thread tile 8x8 (rows ty*4/32+ty*4 quads,
// cols tx*4/64+tx*4 quads -> all LDS conflict-free at 16B stride).
template <int M, int N, int KTOT>
__global__ __launch_bounds__(128, 4) void gemm_kernel(
    const float* __restrict__ X,
    const float* __restrict__ W,
    float* __restrict__ part)
{
    constexpr int BK  = 16;
    constexpr int BM  = 64;
    constexpr int BN  = 128;
    constexpr int NT  = KCHUNK / BK;       // 32 tiles in this CTA's chunk
    constexpr int XLD = BM * BK / 128;     // 8
    constexpr int WLD = BN * BK / 128;     // 16

    __shared__ __align__(16) float Xs[2][BK][BM + 4];
    __shared__ __align__(16) float Ws[2][BK][BN + 4];

    const int tid = threadIdx.x;
    const int m0 = blockIdx.y * BM;
    const int n0 = blockIdx.x * BN;
    const int kbase = blockIdx.z * KCHUNK;

    const int lk = tid % BK;
    const int lr = tid / BK;               // 0..7
    const float* Xp = X + (size_t)(m0 + lr) * KTOT + kbase + lk;
    const float* Wp = W + (size_t)(n0 + lr) * KTOT + kbase + lk;

    const int tx = tid % 16;
    const int ty = tid / 16;               // 0..7

    float xr[XLD], wr[WLD];
    // acc[i][j]: i=0..3 rows ty*4+i ; i=4..7 rows 32+ty*4+(i-4)
    //            j=0,1 cols tx*4+{0,1},{2,3} ; j=2,3 cols 64+tx*4+{0,1},{2,3}
    unsigned long long acc[8][4];
#pragma unroll
    for (int i = 0; i < 8; i++)
#pragma unroll
        for (int j = 0; j < 4; j++) acc[i][j] = 0ull;

    // prologue: tile0 -> regs -> buf0 ; tile1 -> regs (in flight)
#pragma unroll
    for (int i = 0; i < XLD; i++) xr[i] = Xp[(size_t)i * 8 * KTOT];
#pragma unroll
    for (int i = 0; i < WLD; i++) wr[i] = Wp[(size_t)i * 8 * KTOT];
#pragma unroll
    for (int i = 0; i < XLD; i++) Xs[0][lk][lr + i * 8] = xr[i];
#pragma unroll
    for (int i = 0; i < WLD; i++) Ws[0][lk][lr + i * 8] = wr[i];
#pragma unroll
    for (int i = 0; i < XLD; i++) xr[i] = Xp[(size_t)i * 8 * KTOT + BK];
#pragma unroll
    for (int i = 0; i < WLD; i++) wr[i] = Wp[(size_t)i * 8 * KTOT + BK];
    __syncthreads();

    for (int t = 0; t < NT; t++) {
        const int cur = t & 1;
        if (t + 1 < NT) {
#pragma unroll
            for (int i = 0; i < XLD; i++) Xs[cur ^ 1][lk][lr + i * 8] = xr[i];
#pragma unroll
            for (int i = 0; i < WLD; i++) Ws[cur ^ 1][lk][lr + i * 8] = wr[i];
        }
        if (t + 2 < NT) {
#pragma unroll
            for (int i = 0; i < XLD; i++) xr[i] = Xp[(size_t)i * 8 * KTOT + (t + 2) * BK];
#pragma unroll
            for (int i = 0; i < WLD; i++) wr[i] = Wp[(size_t)i * 8 * KTOT + (t + 2) * BK];
        }

#pragma unroll
        for (int kk = 0; kk < BK; kk++) {
            float4 xa = *reinterpret_cast<const float4*>(&Xs[cur][kk][ty * 4]);
            float4 xb = *reinterpret_cast<const float4*>(&Xs[cur][kk][32 + ty * 4]);
            ulonglong2 wA = *reinterpret_cast<const ulonglong2*>(&Ws[cur][kk][tx * 4]);
            ulonglong2 wB = *reinterpret_cast<const ulonglong2*>(&Ws[cur][kk][64 + tx * 4]);
            unsigned long long aa[8];
            DUP2(aa[0], xa.x); DUP2(aa[1], xa.y); DUP2(aa[2], xa.z); DUP2(aa[3], xa.w);
            DUP2(aa[4], xb.x); DUP2(aa[5], xb.y); DUP2(aa[6], xb.z); DUP2(aa[7], xb.w);
#pragma unroll
            for (int i = 0; i < 8; i++) {
                FMA2(acc[i][0], aa[i], wA.x);
                FMA2(acc[i][1], aa[i], wA.y);
                FMA2(acc[i][2], aa[i], wB.x);
                FMA2(acc[i][3], aa[i], wB.y);
            }
        }
        __syncthreads();
    }

    // epilogue: store this chunk's raw partial sums
    float* base = part + (size_t)blockIdx.z * M * N;
#pragma unroll
    for (int i = 0; i < 8; i++) {
        int m = (i < 4) ? (m0 + ty * 4 + i) : (m0 + 32 + ty * 4 + (i - 4));
        float* orow = base + (size_t)m * N + n0;
#pragma unroll
        for (int h = 0; h < 2; h++) {   // h=0 -> cols tx*4 ; h=1 -> 64+tx*4
            float4 f4;
            f4.x = __uint_as_float((uint32_t)(acc[i][2 * h] & 0xFFFFFFFFull));
            f4.y = __uint_as_float((uint32_t)(acc[i][2 * h] >> 32));
            f4.z = __uint_as_float((uint32_t)(acc[i][2 * h + 1] & 0xFFFFFFFFull));
            f4.w = __uint_as_float((uint32_t)(acc[i][2 * h + 1] >> 32));
            *reinterpret_cast<float4*>(orow + h * 64 + tx * 4) = f4;
        }
    }
}

// ---------------- launcher ----------------
extern "C" void kernel_launch(void* const* d_in, const int* in_sizes, int n_in,
                              void* d_out, int out_size) {
    (void)in_sizes; (void)n_in; (void)out_size;
    const float* sd  = (const float*)d_in[0];
    const float* h0v = (const float*)d_in[1];
    const float* h0s = (const float*)d_in[2];
    const float* h1v = (const float*)d_in[3];
    const float* h1s = (const float*)d_in[4];
    const float* ov  = (const float*)d_in[5];
    const float* os  = (const float*)d_in[6];
    const float* W0  = (const float*)d_in[7];
    const float* b0  = (const float*)d_in[8];
    const float* W1  = (const float*)d_in[9];
    const float* b1  = (const float*)d_in[10];
    const float* Wo  = (const float*)d_in[11];
    const float* bo  = (const float*)d_in[12];
    float* out = (float*)d_out;

    float *xt, *p0, *s0all, *p1, *s1all, *po;
    cudaGetSymbolAddress((void**)&xt,    g_xt);
    cudaGetSymbolAddress((void**)&p0,    g_p0);
    cudaGetSymbolAddress((void**)&s0all, g_s0all);
    cudaGetSymbolAddress((void**)&p1,    g_p1);
    cudaGetSymbolAddress((void**)&s1all, g_s1all);
    cudaGetSymbolAddress((void**)&po,    g_po);

    // 1) transpose input [B,K,T] -> [T,B,K]
    {
        dim3 tb(32, 8);
        dim3 tg(IN_DIM / 32, BATCH);
        transpose_kernel<<<tg, tb>>>(sd);
    }

    // 2) layer0 GEMM (split-K chunks, M = T*B = 4096)
    {
        dim3 grid(HID / 128, TB / 64, 4);   // (16, 64, 4) = 4096 CTAs
        gemm_kernel<TB, HID, IN_DIM><<<grid, 128>>>(xt, W0, p0);
    }

    // 3) layer0 LIF scan (folds partials)
    lif_scan_kernel<HID><<<(BATCH * HID + 255) / 256, 256>>>(p0, s0all, h0v, h0s, b0);

    // 4) layer1 GEMM
    {
        dim3 grid(HID / 128, TB / 64, 4);
        gemm_kernel<TB, HID, HID><<<grid, 128>>>(s0all, W1, p1);
    }

    // 5) layer1 LIF scan
    lif_scan_kernel<HID><<<(BATCH * HID + 255) / 256, 256>>>(p1, s1all, h1v, h1s, b1);

    // 6) output-layer GEMM
    {
        dim3 grid(OUT_DIM / 128, TB / 64, 4);   // (4, 64, 4) = 1024 CTAs
        gemm_kernel<TB, OUT_DIM, HID><<<grid, 128>>>(s1all, Wo, po);
    }

    // 7) output LIF scan + spike-count accumulation
    lifo_scan_kernel<<<(BATCH * OUT_DIM + 255) / 256, 256>>>(po, ov, os, bo, out);
}

// round 12
// speedup vs baseline: 2.1970x; 1.1105x over previous
#include <cuda_runtime.h>
#include <cstdint>

// Problem constants (fixed by the dataset)
#define BATCH   128
#define IN_DIM  2048
#define HID     2048
#define OUT_DIM 512
#define TSTEPS  32
#define VDECAY  0.5f
#define VTH     0.5f
#define KCHUNK  512   // reference split-K chunk (bit-exact contract from R2)

#define TB (TSTEPS * BATCH)   // 4096 batched rows

// ---------------- device scratch (no allocations allowed) ----------------
__device__ float g_xt[TB * IN_DIM];          // [T*B, K] transposed input
__device__ float g_p0[4 * TB * HID];         // layer0 chunk partials [z][T*B, H]
__device__ float g_s0all[TB * HID];          // layer0 spikes per t
__device__ float g_p1[4 * TB * HID];         // layer1 chunk partials
__device__ float g_s1all[TB * HID];          // layer1 spikes per t
__device__ float g_po[4 * TB * OUT_DIM];     // output-layer chunk partials
__device__ float g_w0t[IN_DIM * HID];        // W0 transposed: [k][n]
__device__ float g_w1t[HID * HID];           // W1 transposed: [k][n]
__device__ float g_wot[HID * OUT_DIM];       // Wo transposed: [k][n]

// packed f32x2 ops: two independent IEEE-RN operations per instruction ->
// per-element rounding identical to scalar chains (validated bit-exact in R8).
#define FMA2(accv, av, wv) \
    asm("fma.rn.f32x2 %0, %1, %2, %0;" : "+l"(accv) : "l"(av), "l"(wv))
#define DUP2(dst, fval) \
    asm("mov.b64 %0, {%1, %1};" : "=l"(dst) : "r"(__float_as_uint(fval)))
#define CP_ASYNC16(dst_u32, src_ptr) \
    asm volatile("cp.async.cg.shared.global [%0], [%1], 16;" :: "r"(dst_u32), "l"(src_ptr))
#define CP_COMMIT() asm volatile("cp.async.commit_group;" ::: "memory")
#define CP_WAIT0()  asm volatile("cp.async.wait_group 0;" ::: "memory")

__device__ __forceinline__ uint32_t smem_u32(const void* p) {
    return (uint32_t)__cvta_generic_to_shared(p);
}

// ---------------- transpose spike_data [B, K, T] -> [T, B, K] ----------------
__global__ void transpose_kernel(const float* __restrict__ sd) {
    __shared__ float tile[32][33];
    int b  = blockIdx.y;
    int k0 = blockIdx.x * 32;
    int tx = threadIdx.x;
    int ty = threadIdx.y;
#pragma unroll
    for (int i = 0; i < 4; i++) {
        int kl = ty + i * 8;
        tile[kl][tx] = sd[(b * IN_DIM + k0 + kl) * TSTEPS + tx];
    }
    __syncthreads();
#pragma unroll
    for (int i = 0; i < 4; i++) {
        int t = ty + i * 8;
        g_xt[(t * BATCH + b) * IN_DIM + k0 + tx] = tile[tx][t];
    }
}

// ---------------- weight transpose: in[R][C] -> out[C][R] ----------------
template <int R, int C>
__global__ void wtrans_kernel(const float* __restrict__ in, float* __restrict__ out) {
    __shared__ float tile[32][33];
    int c0 = blockIdx.x * 32;
    int r0 = blockIdx.y * 32;
    int tx = threadIdx.x;
    int ty = threadIdx.y;
#pragma unroll
    for (int i = 0; i < 4; i++)
        tile[ty + i * 8][tx] = in[(size_t)(r0 + ty + i * 8) * C + c0 + tx];
    __syncthreads();
#pragma unroll
    for (int i = 0; i < 4; i++)
        out[(size_t)(c0 + ty + i * 8) * R + r0 + tx] = tile[tx][ty + i * 8];
}

// ---------------- LIF scan over time (folds 4 chunk partials) ----------------
// g = ((p0+p1)+p2)+p3 left-assoc (== in-kernel fold since 0+c0 rounds to c0);
// then v = (0.5*v*(1-s) + g) + bias ; s = (v > VTH). Bit-exact contract.
template <int N>
__global__ void lif_scan_kernel(const float* __restrict__ pin,   // [4][T*B*N]
                                float* __restrict__ sall,        // [T, B*N]
                                const float* __restrict__ v0in,
                                const float* __restrict__ s0in,
                                const float* __restrict__ bias) {
    int idx = blockIdx.x * blockDim.x + threadIdx.x;
    if (idx >= BATCH * N) return;
    const size_t PL = (size_t)TB * N;    // plane stride
    float vv = v0in[idx];
    float ss = s0in[idx];
    float bb = bias[idx % N];
#pragma unroll
    for (int t = 0; t < TSTEPS; t++) {
        size_t o = (size_t)t * BATCH * N + idx;
        float g = __fadd_rn(__fadd_rn(__fadd_rn(pin[o], pin[PL + o]), pin[2 * PL + o]),
                            pin[3 * PL + o]);
        float decay = __fmul_rn(__fmul_rn(VDECAY, vv), __fadd_rn(1.0f, -ss));
        vv = __fadd_rn(__fadd_rn(decay, g), bb);
        ss = (vv > VTH) ? 1.0f : 0.0f;
        sall[o] = ss;
    }
}

// ---------------- output-layer LIF scan: fold partials + spike counts ----------------
__global__ void lifo_scan_kernel(const float* __restrict__ pin,  // [4][T*B*OUT]
                                 const float* __restrict__ v0in,
                                 const float* __restrict__ s0in,
                                 const float* __restrict__ bias,
                                 float* __restrict__ out) {
    int idx = blockIdx.x * blockDim.x + threadIdx.x;
    if (idx >= BATCH * OUT_DIM) return;
    const size_t PL = (size_t)TB * OUT_DIM;
    float vv = v0in[idx];
    float ss = s0in[idx];
    float bb = bias[idx % OUT_DIM];
    float acc = 0.0f;
#pragma unroll
    for (int t = 0; t < TSTEPS; t++) {
        size_t o = (size_t)t * BATCH * OUT_DIM + idx;
        float g = __fadd_rn(__fadd_rn(__fadd_rn(pin[o], pin[PL + o]), pin[2 * PL + o]),
                            pin[3 * PL + o]);
        float decay = __fmul_rn(__fmul_rn(VDECAY, vv), __fadd_rn(1.0f, -ss));
        vv = __fadd_rn(__fadd_rn(decay, g), bb);
        ss = (vv > VTH) ? 1.0f : 0.0f;
        acc += ss;
    }
    out[idx] = acc;
}

// ---------------- split-K chunk GEMM, packed f32x2, TM8xTN8, cp.async W ----------------
// Partial[z][m][n] = sum over k in [z*512, z*512+512) of X[m][k]*Wt[k][n],
// serial in-order FMA per element (bit-exact chunk chain from R2 contract).
// W arrives via cp.async from the k-major transposed copy (no staging regs/STS).
// BM=64, BN=128, 128 threads; thread tile 8x8.
template <int M, int N, int KTOT>
__global__ __launch_bounds__(128, 4) void gemm_kernel(
    const float* __restrict__ X,
    const float* __restrict__ Wt,      // [KTOT][N] k-major
    float* __restrict__ part)
{
    constexpr int BK  = 16;
    constexpr int BM  = 64;
    constexpr int BN  = 128;
    constexpr int NT  = KCHUNK / BK;       // 32 tiles in this CTA's chunk
    constexpr int XLD = BM * BK / 128;     // 8
    constexpr int WPITCH = BN + 4;         // 132 floats per smem W row

    __shared__ __align__(16) float Xs[2][BK][BM + 4];
    __shared__ __align__(16) float Ws[2][BK][WPITCH];

    const int tid = threadIdx.x;
    const int m0 = blockIdx.y * BM;
    const int n0 = blockIdx.x * BN;
    const int kbase = blockIdx.z * KCHUNK;

    const int lk = tid % BK;
    const int lr = tid / BK;               // 0..7
    const float* Xp = X + (size_t)(m0 + lr) * KTOT + kbase + lk;

    // cp.async W mapping: 512 x 16B chunks per tile; thread does 4.
    // chunk id = tid + i*128 ; row = id/32 (k within tile), c16 = id%32.
    const int wrow0 = tid / 32;            // rows wrow0, wrow0+4, +8, +12
    const int wc16  = tid % 32;
    const float* Wp = Wt + (size_t)(kbase + wrow0) * N + n0 + wc16 * 4;

    const int tx = tid % 16;
    const int ty = tid / 16;               // 0..7

    float xr[XLD];
    unsigned long long acc[8][4];
#pragma unroll
    for (int i = 0; i < 8; i++)
#pragma unroll
        for (int j = 0; j < 4; j++) acc[i][j] = 0ull;

    // prologue: W tile0 via cp.async ; X tile0 regs->smem ; X tile1 regs
    {
        uint32_t wdst = smem_u32(&Ws[0][wrow0][wc16 * 4]);
#pragma unroll
        for (int i = 0; i < 4; i++)
            CP_ASYNC16(wdst + i * 4 * WPITCH * 4, Wp + (size_t)i * 4 * N);
        CP_COMMIT();
    }
#pragma unroll
    for (int i = 0; i < XLD; i++) xr[i] = Xp[(size_t)i * 8 * KTOT];
#pragma unroll
    for (int i = 0; i < XLD; i++) Xs[0][lk][lr + i * 8] = xr[i];
#pragma unroll
    for (int i = 0; i < XLD; i++) xr[i] = Xp[(size_t)i * 8 * KTOT + BK];
    CP_WAIT0();
    __syncthreads();

    for (int t = 0; t < NT; t++) {
        const int cur = t & 1;
        const int nxt = cur ^ 1;
        if (t + 1 < NT) {
            // W tile t+1 -> free buffer via cp.async (in flight during compute)
            uint32_t wdst = smem_u32(&Ws[nxt][wrow0][wc16 * 4]);
            const float* wsrc = Wp + (size_t)(t + 1) * BK * N;
#pragma unroll
            for (int i = 0; i < 4; i++)
                CP_ASYNC16(wdst + i * 4 * WPITCH * 4, wsrc + (size_t)i * 4 * N);
            CP_COMMIT();
            // X tile t+1 regs -> free buffer
#pragma unroll
            for (int i = 0; i < XLD; i++) Xs[nxt][lk][lr + i * 8] = xr[i];
        }
        if (t + 2 < NT) {
#pragma unroll
            for (int i = 0; i < XLD; i++) xr[i] = Xp[(size_t)i * 8 * KTOT + (t + 2) * BK];
        }

#pragma unroll
        for (int kk = 0; kk < BK; kk++) {
            float4 xa = *reinterpret_cast<const float4*>(&Xs[cur][kk][ty * 4]);
            float4 xb = *reinterpret_cast<const float4*>(&Xs[cur][kk][32 + ty * 4]);
            ulonglong2 wA = *reinterpret_cast<const ulonglong2*>(&Ws[cur][kk][tx * 4]);
            ulonglong2 wB = *reinterpret_cast<const ulonglong2*>(&Ws[cur][kk][64 + tx * 4]);
            unsigned long long aa[8];
            DUP2(aa[0], xa.x); DUP2(aa[1], xa.y); DUP2(aa[2], xa.z); DUP2(aa[3], xa.w);
            DUP2(aa[4], xb.x); DUP2(aa[5], xb.y); DUP2(aa[6], xb.z); DUP2(aa[7], xb.w);
#pragma unroll
            for (int i = 0; i < 8; i++) {
                FMA2(acc[i][0], aa[i], wA.x);
                FMA2(acc[i][1], aa[i], wA.y);
                FMA2(acc[i][2], aa[i], wB.x);
                FMA2(acc[i][3], aa[i], wB.y);
            }
        }

        if (t + 1 < NT) CP_WAIT0();
        __syncthreads();
    }

    // epilogue: store this chunk's raw partial sums
    float* base = part + (size_t)blockIdx.z * M * N;
#pragma unroll
    for (int i = 0; i < 8; i++) {
        int m = (i < 4) ? (m0 + ty * 4 + i) : (m0 + 32 + ty * 4 + (i - 4));
        float* orow = base + (size_t)m * N + n0;
#pragma unroll
        for (int h = 0; h < 2; h++) {   // h=0 -> cols tx*4 ; h=1 -> 64+tx*4
            float4 f4;
            f4.x = __uint_as_float((uint32_t)(acc[i][2 * h] & 0xFFFFFFFFull));
            f4.y = __uint_as_float((uint32_t)(acc[i][2 * h] >> 32));
            f4.z = __uint_as_float((uint32_t)(acc[i][2 * h + 1] & 0xFFFFFFFFull));
            f4.w = __uint_as_float((uint32_t)(acc[i][2 * h + 1] >> 32));
            *reinterpret_cast<float4*>(orow + h * 64 + tx * 4) = f4;
        }
    }
}

// ---------------- launcher ----------------
extern "C" void kernel_launch(void* const* d_in, const int* in_sizes, int n_in,
                              void* d_out, int out_size) {
    (void)in_sizes; (void)n_in; (void)out_size;
    const float* sd  = (const float*)d_in[0];
    const float* h0v = (const float*)d_in[1];
    const float* h0s = (const float*)d_in[2];
    const float* h1v = (const float*)d_in[3];
    const float* h1s = (const float*)d_in[4];
    const float* ov  = (const float*)d_in[5];
    const float* os  = (const float*)d_in[6];
    const float* W0  = (const float*)d_in[7];
    const float* b0  = (const float*)d_in[8];
    const float* W1  = (const float*)d_in[9];
    const float* b1  = (const float*)d_in[10];
    const float* Wo  = (const float*)d_in[11];
    const float* bo  = (const float*)d_in[12];
    float* out = (float*)d_out;

    float *xt, *p0, *s0all, *p1, *s1all, *po, *w0t, *w1t, *wot;
    cudaGetSymbolAddress((void**)&xt,    g_xt);
    cudaGetSymbolAddress((void**)&p0,    g_p0);
    cudaGetSymbolAddress((void**)&s0all, g_s0all);
    cudaGetSymbolAddress((void**)&p1,    g_p1);
    cudaGetSymbolAddress((void**)&s1all, g_s1all);
    cudaGetSymbolAddress((void**)&po,    g_po);
    cudaGetSymbolAddress((void**)&w0t,   g_w0t);
    cudaGetSymbolAddress((void**)&w1t,   g_w1t);
    cudaGetSymbolAddress((void**)&wot,   g_wot);

    // 0) weight transposes (k-major for cp.async)
    {
        dim3 tb(32, 8);
        dim3 g0(IN_DIM / 32, HID / 32);
        wtrans_kernel<HID, IN_DIM><<<g0, tb>>>(W0, w0t);
        dim3 g1(HID / 32, HID / 32);
        wtrans_kernel<HID, HID><<<g1, tb>>>(W1, w1t);
        dim3 g2(HID / 32, OUT_DIM / 32);
        wtrans_kernel<OUT_DIM, HID><<<g2, tb>>>(Wo, wot);
    }

    // 1) transpose input [B,K,T] -> [T,B,K]
    {
        dim3 tb(32, 8);
        dim3 tg(IN_DIM / 32, BATCH);
        transpose_kernel<<<tg, tb>>>(sd);
    }

    // 2) layer0 GEMM (split-K chunks, M = T*B = 4096)
    {
        dim3 grid(HID / 128, TB / 64, 4);   // (16, 64, 4) = 4096 CTAs
        gemm_kernel<TB, HID, IN_DIM><<<grid, 128>>>(xt, w0t, p0);
    }

    // 3) layer0 LIF scan (folds partials)
    lif_scan_kernel<HID><<<(BATCH * HID + 255) / 256, 256>>>(p0, s0all, h0v, h0s, b0);

    // 4) layer1 GEMM
    {
        dim3 grid(HID / 128, TB / 64, 4);
        gemm_kernel<TB, HID, HID><<<grid, 128>>>(s0all, w1t, p1);
    }

    // 5) layer1 LIF scan
    lif_scan_kernel<HID><<<(BATCH * HID + 255) / 256, 256>>>(p1, s1all, h1v, h1s, b1);

    // 6) output-layer GEMM
    {
        dim3 grid(OUT_DIM / 128, TB / 64, 4);   // (4, 64, 4) = 1024 CTAs
        gemm_kernel<TB, OUT_DIM, HID><<<grid, 128>>>(s1all, wot, po);
    }

    // 7) output LIF scan + spike-count accumulation
    lifo_scan_kernel<<<(BATCH * OUT_DIM + 255) / 256, 256>>>(po, ov, os, bo, out);
}